// round 14
// baseline (speedup 1.0000x reference)
#include <cuda_runtime.h>
#include <cuda_fp16.h>
#include <cstdint>

#define Bsz   16
#define CIN   512
#define COUT  512
#define SDIM  512
#define HWDIM 32

// ---------------- scratch (__device__ globals; no allocations) --------------
__device__ float g_s[Bsz * CIN];            // modulation s[b,i]
__device__ float g_d[Bsz * COUT];           // demod d[b,o]
__device__ float g_wsq[COUT * CIN];         // sum_k cw^2
__device__ __align__(16) __half g_w16[9 * COUT * CIN];          // [kk][o][ic]
__device__ __align__(16) __half g_x16[Bsz * 34 * 34 * CIN];     // [b][yy][xx][ic], zero halo

// ---------------- PTX helpers (base ISA only) --------------------------------
__device__ __forceinline__ uint32_t smem_u32(const void* p) {
    uint32_t a;
    asm("{ .reg .u64 t; cvta.to.shared.u64 t, %1; cvt.u32.u64 %0, t; }"
        : "=r"(a) : "l"(p));
    return a;
}
__device__ __forceinline__ void cp16(uint32_t s, const void* g) {
    asm volatile("cp.async.cg.shared.global [%0], [%1], 16;" :: "r"(s), "l"(g));
}
#define CP_COMMIT() asm volatile("cp.async.commit_group;" ::: "memory")
#define CP_WAIT0()  asm volatile("cp.async.wait_group 0;" ::: "memory")

__device__ __forceinline__ void ldsm_x4(uint32_t* r, uint32_t addr) {
    asm volatile("ldmatrix.sync.aligned.m8n8.x4.shared.b16 {%0,%1,%2,%3}, [%4];"
        : "=r"(r[0]), "=r"(r[1]), "=r"(r[2]), "=r"(r[3]) : "r"(addr));
}
__device__ __forceinline__ void mma16816(float* c, const uint32_t* a, const uint32_t* b) {
    asm volatile("mma.sync.aligned.m16n8k16.row.col.f32.f16.f16.f32 "
        "{%0,%1,%2,%3}, {%4,%5,%6,%7}, {%8,%9}, {%0,%1,%2,%3};"
        : "+f"(c[0]), "+f"(c[1]), "+f"(c[2]), "+f"(c[3])
        : "r"(a[0]), "r"(a[1]), "r"(a[2]), "r"(a[3]), "r"(b[0]), "r"(b[1]));
}

// ---------------------------------------------------------------------------
// K1: prep_w (blocks 0..1023) ∪ style (blocks 1024..1087). block(256)
//   prep_w: smem-staged coalesced float4 reads of cw, then per-thread 9 vals.
//   style:  s[b,i] = style @ (aff_w/sqrt(512))^T + bias + 1   (warp-per-row)
// ---------------------------------------------------------------------------
__global__ void k_prep1(const float* __restrict__ cw,
                        const float* __restrict__ style,
                        const float* __restrict__ aff_w,
                        const float* __restrict__ aff_b) {
    __shared__ float sw[2304];              // 256 idx * 9 floats
    const int tid = threadIdx.x;
    if (blockIdx.x < 1024) {
        // ---- coalesced stage: 576 float4 per block ----
        const float4* __restrict__ src =
            reinterpret_cast<const float4*>(cw + (long)blockIdx.x * 2304);
        float4* dst4 = reinterpret_cast<float4*>(sw);
#pragma unroll
        for (int i = 0; i < 3; i++) {
            const int j = i * 256 + tid;
            if (j < 576) dst4[j] = src[j];
        }
        __syncthreads();
        const int idx = blockIdx.x * 256 + tid;   // o*512+ic
        const float* __restrict__ p = sw + tid * 9;  // stride 9: conflict-free
        float v[9];
        float s = 0.f;
#pragma unroll
        for (int k = 0; k < 9; k++) { v[k] = p[k]; s += v[k] * v[k]; }
        g_wsq[idx] = s;
#pragma unroll
        for (int kk = 0; kk < 9; kk++)
            g_w16[kk * (COUT * CIN) + idx] = __float2half(v[kk]);
        return;
    }
    // ---- style: block handles (b, quarter) ----
    float* st = sw;                         // reuse smem
    const int blk = blockIdx.x - 1024;      // 0..63
    const int b = blk >> 2;
    const int quarter = blk & 3;
    const int lane = tid & 31, w = tid >> 5;
    for (int j = tid; j < SDIM; j += 256) st[j] = style[b * SDIM + j];
    __syncthreads();
    const float4* __restrict__ st4 = reinterpret_cast<const float4*>(st);
    const float aff_scale = 0.04419417382415922f;  // 1/sqrt(512)
#pragma unroll
    for (int rr = 0; rr < 16; rr++) {
        const int i = quarter * 128 + w * 16 + rr;
        const float4* __restrict__ wrow =
            reinterpret_cast<const float4*>(aff_w + (long)i * SDIM);
        float acc = 0.f;
#pragma unroll
        for (int it = 0; it < 4; it++) {
            const float4 v = wrow[it * 32 + lane];
            const float4 s = st4[it * 32 + lane];
            acc += v.x * s.x + v.y * s.y + v.z * s.z + v.w * s.w;
        }
#pragma unroll
        for (int off = 16; off; off >>= 1)
            acc += __shfl_xor_sync(0xFFFFFFFFu, acc, off);
        if (lane == 0)
            g_s[b * CIN + i] = acc * aff_scale + aff_b[i] + 1.0f;
    }
}

// ---------------------------------------------------------------------------
// K2: prep_x (y<16) ∪ demod (y==16, z<4). grid(16, 17, 8), block(256)
// ---------------------------------------------------------------------------
__global__ void k_prep2(const float* __restrict__ x) {
    const int tid = threadIdx.x;
    if (blockIdx.y == 16) {
        if (blockIdx.z >= 4) return;
        __shared__ float s2[CIN];
        const int b = blockIdx.x;
        const int lane = tid & 31, w = tid >> 5;
        for (int j = tid; j < CIN; j += 256) {
            const float v = g_s[b * CIN + j];
            s2[j] = v * v;
        }
        __syncthreads();
        const float4* __restrict__ s24 = reinterpret_cast<const float4*>(s2);
#pragma unroll
        for (int rr = 0; rr < 16; rr++) {
            const int o = blockIdx.z * 128 + w * 16 + rr;
            const float4* __restrict__ wr =
                reinterpret_cast<const float4*>(g_wsq + (long)o * CIN);
            float acc = 0.f;
#pragma unroll
            for (int it = 0; it < 4; it++) {
                const float4 v = wr[it * 32 + lane];
                const float4 s = s24[it * 32 + lane];
                acc += v.x * s.x + v.y * s.y + v.z * s.z + v.w * s.w;
            }
#pragma unroll
            for (int off = 16; off; off >>= 1)
                acc += __shfl_xor_sync(0xFFFFFFFFu, acc, off);
            if (lane == 0)
                g_d[b * COUT + o] = rsqrtf(acc * (1.0f / 4608.0f) + 1e-8f);
        }
        return;
    }

    // ---- prep_x ----
    __shared__ float t[32][133];
    __shared__ float sm[32];
    const int b   = blockIdx.x;
    const int ic0 = blockIdx.y * 32;
    const int y0  = blockIdx.z * 4;
    if (tid < 32) sm[tid] = g_s[b * CIN + ic0 + tid];

    if (blockIdx.z == 0) {
#pragma unroll
        for (int i = 0; i < 9; i++) {
            const int idx = i * 256 + tid;
            if (idx < 2112) {
                const int pos  = idx >> 4;
                const int pair = idx & 15;
                int yy, xx;
                if (pos < 34)       { yy = 0;         xx = pos; }
                else if (pos < 68)  { yy = 33;        xx = pos - 34; }
                else if (pos < 100) { yy = pos - 67;  xx = 0; }
                else                { yy = pos - 99;  xx = 33; }
                *reinterpret_cast<__half2*>(
                    g_x16 + (((long)b * 34 + yy) * 34 + xx) * CIN + ic0 + pair * 2) =
                    __floats2half2_rn(0.f, 0.f);
            }
        }
    }
    __syncthreads();

#pragma unroll
    for (int i = 0; i < 4; i++) {
        const int idx = i * 256 + tid;      // 0..1023
        const int ic  = idx >> 5;
        const int p4  = idx & 31;
        const int r   = p4 >> 3, xc4 = (p4 & 7) * 4;
        const float4 v = *reinterpret_cast<const float4*>(
            x + (((long)b * CIN + ic0 + ic) * 32 + y0 + r) * 32 + xc4);
        const float s = sm[ic];
        float* tr = &t[ic][r * 33 + xc4];
        tr[0] = v.x * s; tr[1] = v.y * s; tr[2] = v.z * s; tr[3] = v.w * s;
    }
    __syncthreads();
#pragma unroll
    for (int i = 0; i < 8; i++) {
        const int idx = i * 256 + tid;
        const int p    = idx >> 4;
        const int pair = idx & 15;
        const int r = p >> 5, xc = p & 31;
        const int ic = pair * 2;
        __half2 h = __floats2half2_rn(t[ic][r * 33 + xc], t[ic + 1][r * 33 + xc]);
        *reinterpret_cast<__half2*>(
            g_x16 + (((long)b * 34 + y0 + r + 1) * 34 + xc + 1) * CIN + ic0 + ic) = h;
    }
}

// ---------------------------------------------------------------------------
// Implicit-GEMM conv, tap-reuse B tile + SW128-swizzled smem (stride 128).
// CTA: [M=128 out-ch, N=64 px (2 rows)]. 4 warps (2M x 2N), warp tile 64x32.
// Outer: 8 ic-chunks (K=64). Inner: 9 taps, A double-buffered; ONE B tile
// serves all 9 taps. B frags hoisted; for t>0 they issue BEFORE the A-wait
// (B is resident+published since tap 0) to overlap LDS with DMA drain.
// grid(4, 16, 16), block(128), dyn smem 50,176 B (4 CTAs/SM)
// ---------------------------------------------------------------------------
#define ABUFSZ  16384     // 128 rows * 128B, swizzled
#define BOFF    32768     // B tile offset
#define BROWS   136       // 4 input rows * 34 px
#define SMEMSZ  (BOFF + BROWS * 128)   // 50,176

extern __shared__ unsigned char sbuf_dyn[];

__global__ void __launch_bounds__(128, 4)
k_conv_mma(float* __restrict__ out) {
    const int b  = blockIdx.z;
    const int o0 = blockIdx.x * 128;
    const int y0 = blockIdx.y * 2;
    const int tid  = threadIdx.x;
    const int lane = tid & 31;
    const int wid  = tid >> 5;
    const int wm   = wid >> 1;     // 0..1  (M)
    const int wn   = wid & 1;      // 0..1  (N)

    const uint32_t sb = smem_u32(sbuf_dyn);
    const uint32_t sB = sb + BOFF;

    const int seg = tid & 7;
    const int r   = tid >> 3;
    const int swA = (seg ^ (r & 7)) << 4;

    float acc[4][4][4];
#pragma unroll
    for (int i = 0; i < 4; i++)
#pragma unroll
        for (int j = 0; j < 4; j++)
#pragma unroll
            for (int k = 0; k < 4; k++) acc[i][j][k] = 0.f;

    int rowc[2];
#pragma unroll
    for (int g = 0; g < 2; g++) {
        const int n = wn * 32 + g * 16 + ((lane >> 4) << 3) + (lane & 7);
        rowc[g] = (n >> 5) * 34 + (n & 31);
    }
    const int colB = (lane >> 3) & 1;
    const int colA = lane >> 4;
    const int rowA_loc = lane & 15;

    auto prefetch_A = [&](int t, int ic0, int st) {
        const uint32_t sa = sb + st * ABUFSZ;
        const __half* __restrict__ wa =
            g_w16 + (long)t * (COUT * CIN) + ic0 + seg * 8;
#pragma unroll
        for (int k8 = 0; k8 < 8; k8++) {
            const int row = r + k8 * 16;
            cp16(sa + row * 128 + swA, wa + (long)(o0 + row) * CIN);
        }
    };

    auto load_B = [&](int ic0) {
#pragma unroll
        for (int it = 0; it < 9; it++) {
            const int idx = it * 128 + tid;
            if (it < 8 || idx < 1088) {
                const int rr = idx >> 3;
                const int s  = idx & 7;
                const int yy = rr / 34;
                const int xx = rr - yy * 34;
                cp16(sB + rr * 128 + ((s ^ (rr & 7)) << 4),
                     g_x16 + (((long)b * 34 + y0 + yy) * 34 + xx) * CIN + ic0 + s * 8);
            }
        }
    };

    auto load_bfrag = [&](uint32_t bfrag[4][2][4], int roff) {
#pragma unroll
        for (int g = 0; g < 2; g++) {
            const int row = rowc[g] + roff;
            const uint32_t base = sB + row * 128;
            const uint32_t b7   = (uint32_t)(row & 7) << 4;
#pragma unroll
            for (int kh = 0; kh < 4; kh++) {
                const uint32_t unit = (uint32_t)(kh * 2 + colB) << 4;
                ldsm_x4(bfrag[kh][g], base + (unit ^ b7));
            }
        }
    };

    load_B(0);
    prefetch_A(0, 0, 0);
    CP_COMMIT();

    int i = 0;
    for (int q = 0; q < 8; q++) {
        for (int t = 0; t < 9; t++, i++) {
            const int st = i & 1;
            const int ky = t / 3, kx = t - ky * 3;
            const int roff = ky * 34 + kx;

            uint32_t bfrag[4][2][4];
            if (t > 0) load_bfrag(bfrag, roff);   // B resident: overlap A-wait

            CP_WAIT0();
            __syncthreads();
            if (i + 1 < 72) {
                const int tn = (t + 1 < 9) ? t + 1 : 0;
                const int qn = (t + 1 < 9) ? q : q + 1;
                prefetch_A(tn, qn * 64, st ^ 1);
            }
            CP_COMMIT();

            if (t == 0) load_bfrag(bfrag, roff);  // new B tile just published

            const uint32_t A = sb + st * ABUFSZ;
#pragma unroll
            for (int kh = 0; kh < 4; kh++) {
                uint32_t af[4][4];
#pragma unroll
                for (int mt = 0; mt < 4; mt++) {
                    const int row = wm * 64 + mt * 16 + rowA_loc;
                    const uint32_t unit = (uint32_t)(kh * 2 + colA) << 4;
                    ldsm_x4(af[mt], A + row * 128 + (unit ^ (((uint32_t)(row & 7)) << 4)));
                }
#pragma unroll
                for (int mt = 0; mt < 4; mt++)
#pragma unroll
                    for (int nt = 0; nt < 4; nt++)
                        mma16816(acc[mt][nt], af[mt], bfrag[kh][nt >> 1] + (nt & 1) * 2);
            }

            if (t == 8 && q < 7) {
                __syncthreads();
                load_B((q + 1) * 64);
                CP_COMMIT();
            }
        }
    }

    const float wsc = 0.014731391274719736f;  // 1/sqrt(4608)
    const int y = y0 + wn;
#pragma unroll
    for (int mt = 0; mt < 4; mt++) {
        const int rr   = wm * 64 + mt * 16 + (lane >> 2);
        const int o_lo = o0 + rr;
        const int o_hi = o_lo + 8;
        const float d0 = g_d[b * COUT + o_lo] * wsc;
        const float d1 = g_d[b * COUT + o_hi] * wsc;
#pragma unroll
        for (int nt = 0; nt < 4; nt++) {
            const int xcol = nt * 8 + (lane & 3) * 2;
            float2 v0 = make_float2(acc[mt][nt][0] * d0, acc[mt][nt][1] * d0);
            float2 v1 = make_float2(acc[mt][nt][2] * d1, acc[mt][nt][3] * d1);
            *reinterpret_cast<float2*>(
                &out[(((long)b * COUT + o_lo) * 32 + y) * 32 + xcol]) = v0;
            *reinterpret_cast<float2*>(
                &out[(((long)b * COUT + o_hi) * 32 + y) * 32 + xcol]) = v1;
        }
    }
}

// ---------------------------------------------------------------------------
extern "C" void kernel_launch(void* const* d_in, const int* in_sizes, int n_in,
                              void* d_out, int out_size) {
    const float* x      = (const float*)d_in[0];  // [16,512,32,32]
    const float* style  = (const float*)d_in[1];  // [16,512]
    const float* aff_w  = (const float*)d_in[2];  // [512,512]
    const float* aff_b  = (const float*)d_in[3];  // [512]
    const float* cw     = (const float*)d_in[4];  // [512,512,3,3]
    float* out          = (float*)d_out;          // [16,512,32,32]

    cudaFuncSetAttribute(k_conv_mma,
                         cudaFuncAttributeMaxDynamicSharedMemorySize,
                         SMEMSZ);

    k_prep1<<<1088, 256>>>(cw, style, aff_w, aff_b);
    k_prep2<<<dim3(Bsz, 17, 8), 256>>>(x);
    k_conv_mma<<<dim3(COUT / 128, 16, Bsz), 128, SMEMSZ>>>(out);
}

// round 15
// speedup vs baseline: 1.1402x; 1.1402x over previous
#include <cuda_runtime.h>
#include <cuda_fp16.h>
#include <cstdint>

#define Bsz   16
#define CIN   512
#define COUT  512
#define SDIM  512
#define HWDIM 32

// ---------------- scratch (__device__ globals; no allocations) --------------
__device__ float g_s[Bsz * CIN];            // modulation s[b,i]
__device__ float g_d[Bsz * COUT];           // demod d[b,o]
__device__ float g_wsq[COUT * CIN];         // sum_k cw^2
__device__ __align__(16) __half g_w16[9 * COUT * CIN];          // [kk][o][ic]
__device__ __align__(16) __half g_x16[Bsz * 34 * 34 * CIN];     // [b][yy][xx][ic], zero halo

// ---------------- PTX helpers (base ISA only) --------------------------------
__device__ __forceinline__ uint32_t smem_u32(const void* p) {
    uint32_t a;
    asm("{ .reg .u64 t; cvta.to.shared.u64 t, %1; cvt.u32.u64 %0, t; }"
        : "=r"(a) : "l"(p));
    return a;
}
__device__ __forceinline__ void cp16(uint32_t s, const void* g) {
    asm volatile("cp.async.cg.shared.global [%0], [%1], 16;" :: "r"(s), "l"(g));
}
#define CP_COMMIT() asm volatile("cp.async.commit_group;" ::: "memory")
#define CP_WAIT0()  asm volatile("cp.async.wait_group 0;" ::: "memory")

__device__ __forceinline__ void ldsm_x4(uint32_t* r, uint32_t addr) {
    asm volatile("ldmatrix.sync.aligned.m8n8.x4.shared.b16 {%0,%1,%2,%3}, [%4];"
        : "=r"(r[0]), "=r"(r[1]), "=r"(r[2]), "=r"(r[3]) : "r"(addr));
}
__device__ __forceinline__ void mma16816(float* c, const uint32_t* a, const uint32_t* b) {
    asm volatile("mma.sync.aligned.m16n8k16.row.col.f32.f16.f16.f32 "
        "{%0,%1,%2,%3}, {%4,%5,%6,%7}, {%8,%9}, {%0,%1,%2,%3};"
        : "+f"(c[0]), "+f"(c[1]), "+f"(c[2]), "+f"(c[3])
        : "r"(a[0]), "r"(a[1]), "r"(a[2]), "r"(a[3]), "r"(b[0]), "r"(b[1]));
}

// ---------------------------------------------------------------------------
// K1: style (blocks 0..63, FIRST — g_s is on K2's critical path) ∪
//     prep_w (blocks 64..1087). block(256)
// ---------------------------------------------------------------------------
__global__ void k_prep1(const float* __restrict__ cw,
                        const float* __restrict__ style,
                        const float* __restrict__ aff_w,
                        const float* __restrict__ aff_b) {
    const int tid = threadIdx.x;
    if (blockIdx.x < 64) {
        // ---- style: block handles (b, quarter), warp-per-row coalesced ----
        __shared__ float st[SDIM];
        const int b = blockIdx.x >> 2;
        const int quarter = blockIdx.x & 3;
        const int lane = tid & 31, w = tid >> 5;
        for (int j = tid; j < SDIM; j += 256) st[j] = style[b * SDIM + j];
        __syncthreads();
        const float4* __restrict__ st4 = reinterpret_cast<const float4*>(st);
        const float aff_scale = 0.04419417382415922f;  // 1/sqrt(512)
#pragma unroll
        for (int rr = 0; rr < 16; rr++) {
            const int i = quarter * 128 + w * 16 + rr;
            const float4* __restrict__ wrow =
                reinterpret_cast<const float4*>(aff_w + (long)i * SDIM);
            float acc = 0.f;
#pragma unroll
            for (int it = 0; it < 4; it++) {
                const float4 v = wrow[it * 32 + lane];
                const float4 s = st4[it * 32 + lane];
                acc += v.x * s.x + v.y * s.y + v.z * s.z + v.w * s.w;
            }
#pragma unroll
            for (int off = 16; off; off >>= 1)
                acc += __shfl_xor_sync(0xFFFFFFFFu, acc, off);
            if (lane == 0)
                g_s[b * CIN + i] = acc * aff_scale + aff_b[i] + 1.0f;
        }
        return;
    }
    // ---- prep_w ----
    const int idx = (blockIdx.x - 64) * 256 + tid;  // o*512+ic
    const float* __restrict__ p = cw + (long)idx * 9;
    float v[9];
    float s = 0.f;
#pragma unroll
    for (int k = 0; k < 9; k++) { v[k] = p[k]; s += v[k] * v[k]; }
    g_wsq[idx] = s;
#pragma unroll
    for (int kk = 0; kk < 9; kk++)
        g_w16[kk * (COUT * CIN) + idx] = __float2half(v[kk]);
}

// ---------------------------------------------------------------------------
// K2: prep_x (y<16) ∪ demod (y==16, z<4). grid(16, 17, 8), block(256)
// ---------------------------------------------------------------------------
__global__ void k_prep2(const float* __restrict__ x) {
    const int tid = threadIdx.x;
    if (blockIdx.y == 16) {
        if (blockIdx.z >= 4) return;
        __shared__ float s2[CIN];
        const int b = blockIdx.x;
        const int lane = tid & 31, w = tid >> 5;
        for (int j = tid; j < CIN; j += 256) {
            const float v = g_s[b * CIN + j];
            s2[j] = v * v;
        }
        __syncthreads();
        const float4* __restrict__ s24 = reinterpret_cast<const float4*>(s2);
#pragma unroll
        for (int rr = 0; rr < 16; rr++) {
            const int o = blockIdx.z * 128 + w * 16 + rr;
            const float4* __restrict__ wr =
                reinterpret_cast<const float4*>(g_wsq + (long)o * CIN);
            float acc = 0.f;
#pragma unroll
            for (int it = 0; it < 4; it++) {
                const float4 v = wr[it * 32 + lane];
                const float4 s = s24[it * 32 + lane];
                acc += v.x * s.x + v.y * s.y + v.z * s.z + v.w * s.w;
            }
#pragma unroll
            for (int off = 16; off; off >>= 1)
                acc += __shfl_xor_sync(0xFFFFFFFFu, acc, off);
            if (lane == 0)
                g_d[b * COUT + o] = rsqrtf(acc * (1.0f / 4608.0f) + 1e-8f);
        }
        return;
    }

    // ---- prep_x ----
    __shared__ float t[32][133];
    __shared__ float sm[32];
    const int b   = blockIdx.x;
    const int ic0 = blockIdx.y * 32;
    const int y0  = blockIdx.z * 4;
    if (tid < 32) sm[tid] = g_s[b * CIN + ic0 + tid];

    if (blockIdx.z == 0) {
#pragma unroll
        for (int i = 0; i < 9; i++) {
            const int idx = i * 256 + tid;
            if (idx < 2112) {
                const int pos  = idx >> 4;
                const int pair = idx & 15;
                int yy, xx;
                if (pos < 34)       { yy = 0;         xx = pos; }
                else if (pos < 68)  { yy = 33;        xx = pos - 34; }
                else if (pos < 100) { yy = pos - 67;  xx = 0; }
                else                { yy = pos - 99;  xx = 33; }
                *reinterpret_cast<__half2*>(
                    g_x16 + (((long)b * 34 + yy) * 34 + xx) * CIN + ic0 + pair * 2) =
                    __floats2half2_rn(0.f, 0.f);
            }
        }
    }
    __syncthreads();

#pragma unroll
    for (int i = 0; i < 4; i++) {
        const int idx = i * 256 + tid;      // 0..1023
        const int ic  = idx >> 5;
        const int p4  = idx & 31;
        const int r   = p4 >> 3, xc4 = (p4 & 7) * 4;
        const float4 v = *reinterpret_cast<const float4*>(
            x + (((long)b * CIN + ic0 + ic) * 32 + y0 + r) * 32 + xc4);
        const float s = sm[ic];
        float* tr = &t[ic][r * 33 + xc4];
        tr[0] = v.x * s; tr[1] = v.y * s; tr[2] = v.z * s; tr[3] = v.w * s;
    }
    __syncthreads();
#pragma unroll
    for (int i = 0; i < 8; i++) {
        const int idx = i * 256 + tid;
        const int p    = idx >> 4;
        const int pair = idx & 15;
        const int r = p >> 5, xc = p & 31;
        const int ic = pair * 2;
        __half2 h = __floats2half2_rn(t[ic][r * 33 + xc], t[ic + 1][r * 33 + xc]);
        *reinterpret_cast<__half2*>(
            g_x16 + (((long)b * 34 + y0 + r + 1) * 34 + xc + 1) * CIN + ic0 + ic) = h;
    }
}

// ---------------------------------------------------------------------------
// Implicit-GEMM conv, tap-reuse B tile + SW128-swizzled smem (stride 128).
// CTA: [M=128 out-ch, N=64 px (2 rows)]. 4 warps (2M x 2N), warp tile 64x32.
// Outer: 8 ic-chunks (K=64). Inner: 9 taps, A double-buffered; ONE B tile
// serves all 9 taps. B frags loaded AFTER wait+sync (R13-proven; hoisting
// them across the wait caused spills at the 128-reg cap -> reverted).
// grid(4, 16, 16), block(128), dyn smem 50,176 B (4 CTAs/SM)   [R13: 175us]
// ---------------------------------------------------------------------------
#define ABUFSZ  16384     // 128 rows * 128B, swizzled
#define BOFF    32768     // B tile offset
#define BROWS   136       // 4 input rows * 34 px
#define SMEMSZ  (BOFF + BROWS * 128)   // 50,176

extern __shared__ unsigned char sbuf_dyn[];

__global__ void __launch_bounds__(128, 4)
k_conv_mma(float* __restrict__ out) {
    const int b  = blockIdx.z;
    const int o0 = blockIdx.x * 128;
    const int y0 = blockIdx.y * 2;
    const int tid  = threadIdx.x;
    const int lane = tid & 31;
    const int wid  = tid >> 5;
    const int wm   = wid >> 1;     // 0..1  (M)
    const int wn   = wid & 1;      // 0..1  (N)

    const uint32_t sb = smem_u32(sbuf_dyn);
    const uint32_t sB = sb + BOFF;

    const int seg = tid & 7;
    const int r   = tid >> 3;
    const int swA = (seg ^ (r & 7)) << 4;

    float acc[4][4][4];
#pragma unroll
    for (int i = 0; i < 4; i++)
#pragma unroll
        for (int j = 0; j < 4; j++)
#pragma unroll
            for (int k = 0; k < 4; k++) acc[i][j][k] = 0.f;

    int rowc[2];
#pragma unroll
    for (int g = 0; g < 2; g++) {
        const int n = wn * 32 + g * 16 + ((lane >> 4) << 3) + (lane & 7);
        rowc[g] = (n >> 5) * 34 + (n & 31);
    }
    const int colB = (lane >> 3) & 1;
    const int colA = lane >> 4;
    const int rowA_loc = lane & 15;

    auto prefetch_A = [&](int t, int ic0, int st) {
        const uint32_t sa = sb + st * ABUFSZ;
        const __half* __restrict__ wa =
            g_w16 + (long)t * (COUT * CIN) + ic0 + seg * 8;
#pragma unroll
        for (int k8 = 0; k8 < 8; k8++) {
            const int row = r + k8 * 16;
            cp16(sa + row * 128 + swA, wa + (long)(o0 + row) * CIN);
        }
    };

    auto load_B = [&](int ic0) {
#pragma unroll
        for (int it = 0; it < 9; it++) {
            const int idx = it * 128 + tid;
            if (it < 8 || idx < 1088) {
                const int rr = idx >> 3;
                const int s  = idx & 7;
                const int yy = rr / 34;
                const int xx = rr - yy * 34;
                cp16(sB + rr * 128 + ((s ^ (rr & 7)) << 4),
                     g_x16 + (((long)b * 34 + y0 + yy) * 34 + xx) * CIN + ic0 + s * 8);
            }
        }
    };

    load_B(0);
    prefetch_A(0, 0, 0);
    CP_COMMIT();

    int i = 0;
    for (int q = 0; q < 8; q++) {
        for (int t = 0; t < 9; t++, i++) {
            const int st = i & 1;
            CP_WAIT0();
            __syncthreads();
            if (i + 1 < 72) {
                const int tn = (t + 1 < 9) ? t + 1 : 0;
                const int qn = (t + 1 < 9) ? q : q + 1;
                prefetch_A(tn, qn * 64, st ^ 1);
            }
            CP_COMMIT();

            const int ky = t / 3, kx = t - ky * 3;
            const int roff = ky * 34 + kx;
            const uint32_t A = sb + st * ABUFSZ;

            uint32_t bfrag[4][2][4];
#pragma unroll
            for (int g = 0; g < 2; g++) {
                const int row = rowc[g] + roff;
                const uint32_t base = sB + row * 128;
                const uint32_t b7   = (uint32_t)(row & 7) << 4;
#pragma unroll
                for (int kh = 0; kh < 4; kh++) {
                    const uint32_t unit = (uint32_t)(kh * 2 + colB) << 4;
                    ldsm_x4(bfrag[kh][g], base + (unit ^ b7));
                }
            }

#pragma unroll
            for (int kh = 0; kh < 4; kh++) {
                uint32_t af[4][4];
#pragma unroll
                for (int mt = 0; mt < 4; mt++) {
                    const int row = wm * 64 + mt * 16 + rowA_loc;
                    const uint32_t unit = (uint32_t)(kh * 2 + colA) << 4;
                    ldsm_x4(af[mt], A + row * 128 + (unit ^ (((uint32_t)(row & 7)) << 4)));
                }
#pragma unroll
                for (int mt = 0; mt < 4; mt++)
#pragma unroll
                    for (int nt = 0; nt < 4; nt++)
                        mma16816(acc[mt][nt], af[mt], bfrag[kh][nt >> 1] + (nt & 1) * 2);
            }

            if (t == 8 && q < 7) {
                __syncthreads();
                load_B((q + 1) * 64);
                CP_COMMIT();
            }
        }
    }

    const float wsc = 0.014731391274719736f;  // 1/sqrt(4608)
    const int y = y0 + wn;
#pragma unroll
    for (int mt = 0; mt < 4; mt++) {
        const int rr   = wm * 64 + mt * 16 + (lane >> 2);
        const int o_lo = o0 + rr;
        const int o_hi = o_lo + 8;
        const float d0 = g_d[b * COUT + o_lo] * wsc;
        const float d1 = g_d[b * COUT + o_hi] * wsc;
#pragma unroll
        for (int nt = 0; nt < 4; nt++) {
            const int xcol = nt * 8 + (lane & 3) * 2;
            float2 v0 = make_float2(acc[mt][nt][0] * d0, acc[mt][nt][1] * d0);
            float2 v1 = make_float2(acc[mt][nt][2] * d1, acc[mt][nt][3] * d1);
            *reinterpret_cast<float2*>(
                &out[(((long)b * COUT + o_lo) * 32 + y) * 32 + xcol]) = v0;
            *reinterpret_cast<float2*>(
                &out[(((long)b * COUT + o_hi) * 32 + y) * 32 + xcol]) = v1;
        }
    }
}

// ---------------------------------------------------------------------------
extern "C" void kernel_launch(void* const* d_in, const int* in_sizes, int n_in,
                              void* d_out, int out_size) {
    const float* x      = (const float*)d_in[0];  // [16,512,32,32]
    const float* style  = (const float*)d_in[1];  // [16,512]
    const float* aff_w  = (const float*)d_in[2];  // [512,512]
    const float* aff_b  = (const float*)d_in[3];  // [512]
    const float* cw     = (const float*)d_in[4];  // [512,512,3,3]
    float* out          = (float*)d_out;          // [16,512,32,32]

    cudaFuncSetAttribute(k_conv_mma,
                         cudaFuncAttributeMaxDynamicSharedMemorySize,
                         SMEMSZ);

    k_prep1<<<1088, 256>>>(cw, style, aff_w, aff_b);
    k_prep2<<<dim3(Bsz, 17, 8), 256>>>(x);
    k_conv_mma<<<dim3(COUT / 128, 16, Bsz), 128, SMEMSZ>>>(out);
}

// round 16
// speedup vs baseline: 1.1411x; 1.0008x over previous
#include <cuda_runtime.h>
#include <cuda_fp16.h>
#include <cstdint>

#define Bsz   16
#define CIN   512
#define COUT  512
#define SDIM  512
#define HWDIM 32

// ---------------- scratch (__device__ globals; no allocations) --------------
__device__ float g_s[Bsz * CIN];            // modulation s[b,i]
__device__ float g_d[Bsz * COUT];           // demod d[b,o]
__device__ __align__(16) float g_wsq[COUT * CIN];               // sum_k cw^2
__device__ __align__(16) __half g_w16[9 * COUT * CIN];          // [kk][o][ic]
__device__ __align__(16) __half g_x16[Bsz * 34 * 34 * CIN];     // [b][yy][xx][ic], zero halo

// ---------------- PTX helpers (base ISA only) --------------------------------
__device__ __forceinline__ uint32_t smem_u32(const void* p) {
    uint32_t a;
    asm("{ .reg .u64 t; cvta.to.shared.u64 t, %1; cvt.u32.u64 %0, t; }"
        : "=r"(a) : "l"(p));
    return a;
}
__device__ __forceinline__ void cp16(uint32_t s, const void* g) {
    asm volatile("cp.async.cg.shared.global [%0], [%1], 16;" :: "r"(s), "l"(g));
}
#define CP_COMMIT() asm volatile("cp.async.commit_group;" ::: "memory")
#define CP_WAIT0()  asm volatile("cp.async.wait_group 0;" ::: "memory")

__device__ __forceinline__ void ldsm_x4(uint32_t* r, uint32_t addr) {
    asm volatile("ldmatrix.sync.aligned.m8n8.x4.shared.b16 {%0,%1,%2,%3}, [%4];"
        : "=r"(r[0]), "=r"(r[1]), "=r"(r[2]), "=r"(r[3]) : "r"(addr));
}
__device__ __forceinline__ void mma16816(float* c, const uint32_t* a, const uint32_t* b) {
    asm volatile("mma.sync.aligned.m16n8k16.row.col.f32.f16.f16.f32 "
        "{%0,%1,%2,%3}, {%4,%5,%6,%7}, {%8,%9}, {%0,%1,%2,%3};"
        : "+f"(c[0]), "+f"(c[1]), "+f"(c[2]), "+f"(c[3])
        : "r"(a[0]), "r"(a[1]), "r"(a[2]), "r"(a[3]), "r"(b[0]), "r"(b[1]));
}

// ---------------------------------------------------------------------------
// K1: style (blocks 0..63, FIRST — g_s is on K2's critical path) ∪
//     prep_w (blocks 64..319; 4 rows/thread, all-float4). block(256)
// ---------------------------------------------------------------------------
__global__ void k_prep1(const float* __restrict__ cw,
                        const float* __restrict__ style,
                        const float* __restrict__ aff_w,
                        const float* __restrict__ aff_b) {
    const int tid = threadIdx.x;
    if (blockIdx.x < 64) {
        // ---- style: block handles (b, quarter), warp-per-row coalesced ----
        __shared__ float st[SDIM];
        const int b = blockIdx.x >> 2;
        const int quarter = blockIdx.x & 3;
        const int lane = tid & 31, w = tid >> 5;
        for (int j = tid; j < SDIM; j += 256) st[j] = style[b * SDIM + j];
        __syncthreads();
        const float4* __restrict__ st4 = reinterpret_cast<const float4*>(st);
        const float aff_scale = 0.04419417382415922f;  // 1/sqrt(512)
#pragma unroll
        for (int rr = 0; rr < 16; rr++) {
            const int i = quarter * 128 + w * 16 + rr;
            const float4* __restrict__ wrow =
                reinterpret_cast<const float4*>(aff_w + (long)i * SDIM);
            float acc = 0.f;
#pragma unroll
            for (int it = 0; it < 4; it++) {
                const float4 v = wrow[it * 32 + lane];
                const float4 s = st4[it * 32 + lane];
                acc += v.x * s.x + v.y * s.y + v.z * s.z + v.w * s.w;
            }
#pragma unroll
            for (int off = 16; off; off >>= 1)
                acc += __shfl_xor_sync(0xFFFFFFFFu, acc, off);
            if (lane == 0)
                g_s[b * CIN + i] = acc * aff_scale + aff_b[i] + 1.0f;
        }
        return;
    }
    // ---- prep_w: thread handles 4 consecutive (o,ic) rows = 36 floats ----
    const int idx4 = (blockIdx.x - 64) * 256 + tid;   // 0..65535
    const int i0   = idx4 * 4;                        // first row index
    const float4* __restrict__ src =
        reinterpret_cast<const float4*>(cw) + (long)idx4 * 9;  // 144B aligned
    float4 v4[9];
#pragma unroll
    for (int j = 0; j < 9; j++) v4[j] = src[j];
    const float* f = reinterpret_cast<const float*>(v4);  // f[r*9+k], const-idx

    // wsq for the 4 rows
    float4 wq;
    {
        float s0 = 0.f, s1 = 0.f, s2 = 0.f, s3 = 0.f;
#pragma unroll
        for (int k = 0; k < 9; k++) {
            s0 += f[k] * f[k];
            s1 += f[9 + k] * f[9 + k];
            s2 += f[18 + k] * f[18 + k];
            s3 += f[27 + k] * f[27 + k];
        }
        wq = make_float4(s0, s1, s2, s3);
    }
    reinterpret_cast<float4*>(g_wsq)[idx4] = wq;

    // w16: per tap, 4 consecutive fp16 = one 8B store
#pragma unroll
    for (int kk = 0; kk < 9; kk++) {
        __half2 h01 = __floats2half2_rn(f[kk],      f[9 + kk]);
        __half2 h23 = __floats2half2_rn(f[18 + kk], f[27 + kk]);
        uint2 pack;
        pack.x = *reinterpret_cast<uint32_t*>(&h01);
        pack.y = *reinterpret_cast<uint32_t*>(&h23);
        *reinterpret_cast<uint2*>(g_w16 + (long)kk * (COUT * CIN) + i0) = pack;
    }
}

// ---------------------------------------------------------------------------
// K2: prep_x (y<16) ∪ demod (y==16, z<4). grid(16, 17, 8), block(256)
// ---------------------------------------------------------------------------
__global__ void k_prep2(const float* __restrict__ x) {
    const int tid = threadIdx.x;
    if (blockIdx.y == 16) {
        if (blockIdx.z >= 4) return;
        __shared__ float s2[CIN];
        const int b = blockIdx.x;
        const int lane = tid & 31, w = tid >> 5;
        for (int j = tid; j < CIN; j += 256) {
            const float v = g_s[b * CIN + j];
            s2[j] = v * v;
        }
        __syncthreads();
        const float4* __restrict__ s24 = reinterpret_cast<const float4*>(s2);
#pragma unroll
        for (int rr = 0; rr < 16; rr++) {
            const int o = blockIdx.z * 128 + w * 16 + rr;
            const float4* __restrict__ wr =
                reinterpret_cast<const float4*>(g_wsq + (long)o * CIN);
            float acc = 0.f;
#pragma unroll
            for (int it = 0; it < 4; it++) {
                const float4 v = wr[it * 32 + lane];
                const float4 s = s24[it * 32 + lane];
                acc += v.x * s.x + v.y * s.y + v.z * s.z + v.w * s.w;
            }
#pragma unroll
            for (int off = 16; off; off >>= 1)
                acc += __shfl_xor_sync(0xFFFFFFFFu, acc, off);
            if (lane == 0)
                g_d[b * COUT + o] = rsqrtf(acc * (1.0f / 4608.0f) + 1e-8f);
        }
        return;
    }

    // ---- prep_x ----
    __shared__ float t[32][133];
    __shared__ float sm[32];
    const int b   = blockIdx.x;
    const int ic0 = blockIdx.y * 32;
    const int y0  = blockIdx.z * 4;
    if (tid < 32) sm[tid] = g_s[b * CIN + ic0 + tid];

    if (blockIdx.z == 0) {
#pragma unroll
        for (int i = 0; i < 9; i++) {
            const int idx = i * 256 + tid;
            if (idx < 2112) {
                const int pos  = idx >> 4;
                const int pair = idx & 15;
                int yy, xx;
                if (pos < 34)       { yy = 0;         xx = pos; }
                else if (pos < 68)  { yy = 33;        xx = pos - 34; }
                else if (pos < 100) { yy = pos - 67;  xx = 0; }
                else                { yy = pos - 99;  xx = 33; }
                *reinterpret_cast<__half2*>(
                    g_x16 + (((long)b * 34 + yy) * 34 + xx) * CIN + ic0 + pair * 2) =
                    __floats2half2_rn(0.f, 0.f);
            }
        }
    }
    __syncthreads();

#pragma unroll
    for (int i = 0; i < 4; i++) {
        const int idx = i * 256 + tid;      // 0..1023
        const int ic  = idx >> 5;
        const int p4  = idx & 31;
        const int r   = p4 >> 3, xc4 = (p4 & 7) * 4;
        const float4 v = *reinterpret_cast<const float4*>(
            x + (((long)b * CIN + ic0 + ic) * 32 + y0 + r) * 32 + xc4);
        const float s = sm[ic];
        float* tr = &t[ic][r * 33 + xc4];
        tr[0] = v.x * s; tr[1] = v.y * s; tr[2] = v.z * s; tr[3] = v.w * s;
    }
    __syncthreads();
#pragma unroll
    for (int i = 0; i < 8; i++) {
        const int idx = i * 256 + tid;
        const int p    = idx >> 4;
        const int pair = idx & 15;
        const int r = p >> 5, xc = p & 31;
        const int ic = pair * 2;
        __half2 h = __floats2half2_rn(t[ic][r * 33 + xc], t[ic + 1][r * 33 + xc]);
        *reinterpret_cast<__half2*>(
            g_x16 + (((long)b * 34 + y0 + r + 1) * 34 + xc + 1) * CIN + ic0 + ic) = h;
    }
}

// ---------------------------------------------------------------------------
// Implicit-GEMM conv, tap-reuse B tile + SW128-swizzled smem (stride 128).
// CTA: [M=128 out-ch, N=64 px (2 rows)]. 4 warps (2M x 2N), warp tile 64x32.
// Outer: 8 ic-chunks (K=64). Inner: 9 taps, A double-buffered; ONE B tile
// serves all 9 taps. B frags loaded AFTER wait+sync (R13-proven).
// 128 regs x 128 thr x 4 CTAs == full regfile; config is boxed-optimal.
// grid(4, 16, 16), block(128), dyn smem 50,176 B (4 CTAs/SM)   [~175us]
// ---------------------------------------------------------------------------
#define ABUFSZ  16384     // 128 rows * 128B, swizzled
#define BOFF    32768     // B tile offset
#define BROWS   136       // 4 input rows * 34 px
#define SMEMSZ  (BOFF + BROWS * 128)   // 50,176

extern __shared__ unsigned char sbuf_dyn[];

__global__ void __launch_bounds__(128, 4)
k_conv_mma(float* __restrict__ out) {
    const int b  = blockIdx.z;
    const int o0 = blockIdx.x * 128;
    const int y0 = blockIdx.y * 2;
    const int tid  = threadIdx.x;
    const int lane = tid & 31;
    const int wid  = tid >> 5;
    const int wm   = wid >> 1;     // 0..1  (M)
    const int wn   = wid & 1;      // 0..1  (N)

    const uint32_t sb = smem_u32(sbuf_dyn);
    const uint32_t sB = sb + BOFF;

    const int seg = tid & 7;
    const int r   = tid >> 3;
    const int swA = (seg ^ (r & 7)) << 4;

    float acc[4][4][4];
#pragma unroll
    for (int i = 0; i < 4; i++)
#pragma unroll
        for (int j = 0; j < 4; j++)
#pragma unroll
            for (int k = 0; k < 4; k++) acc[i][j][k] = 0.f;

    int rowc[2];
#pragma unroll
    for (int g = 0; g < 2; g++) {
        const int n = wn * 32 + g * 16 + ((lane >> 4) << 3) + (lane & 7);
        rowc[g] = (n >> 5) * 34 + (n & 31);
    }
    const int colB = (lane >> 3) & 1;
    const int colA = lane >> 4;
    const int rowA_loc = lane & 15;

    auto prefetch_A = [&](int t, int ic0, int st) {
        const uint32_t sa = sb + st * ABUFSZ;
        const __half* __restrict__ wa =
            g_w16 + (long)t * (COUT * CIN) + ic0 + seg * 8;
#pragma unroll
        for (int k8 = 0; k8 < 8; k8++) {
            const int row = r + k8 * 16;
            cp16(sa + row * 128 + swA, wa + (long)(o0 + row) * CIN);
        }
    };

    auto load_B = [&](int ic0) {
#pragma unroll
        for (int it = 0; it < 9; it++) {
            const int idx = it * 128 + tid;
            if (it < 8 || idx < 1088) {
                const int rr = idx >> 3;
                const int s  = idx & 7;
                const int yy = rr / 34;
                const int xx = rr - yy * 34;
                cp16(sB + rr * 128 + ((s ^ (rr & 7)) << 4),
                     g_x16 + (((long)b * 34 + y0 + yy) * 34 + xx) * CIN + ic0 + s * 8);
            }
        }
    };

    load_B(0);
    prefetch_A(0, 0, 0);
    CP_COMMIT();

    int i = 0;
    for (int q = 0; q < 8; q++) {
        for (int t = 0; t < 9; t++, i++) {
            const int st = i & 1;
            CP_WAIT0();
            __syncthreads();
            if (i + 1 < 72) {
                const int tn = (t + 1 < 9) ? t + 1 : 0;
                const int qn = (t + 1 < 9) ? q : q + 1;
                prefetch_A(tn, qn * 64, st ^ 1);
            }
            CP_COMMIT();

            const int ky = t / 3, kx = t - ky * 3;
            const int roff = ky * 34 + kx;
            const uint32_t A = sb + st * ABUFSZ;

            uint32_t bfrag[4][2][4];
#pragma unroll
            for (int g = 0; g < 2; g++) {
                const int row = rowc[g] + roff;
                const uint32_t base = sB + row * 128;
                const uint32_t b7   = (uint32_t)(row & 7) << 4;
#pragma unroll
                for (int kh = 0; kh < 4; kh++) {
                    const uint32_t unit = (uint32_t)(kh * 2 + colB) << 4;
                    ldsm_x4(bfrag[kh][g], base + (unit ^ b7));
                }
            }

#pragma unroll
            for (int kh = 0; kh < 4; kh++) {
                uint32_t af[4][4];
#pragma unroll
                for (int mt = 0; mt < 4; mt++) {
                    const int row = wm * 64 + mt * 16 + rowA_loc;
                    const uint32_t unit = (uint32_t)(kh * 2 + colA) << 4;
                    ldsm_x4(af[mt], A + row * 128 + (unit ^ (((uint32_t)(row & 7)) << 4)));
                }
#pragma unroll
                for (int mt = 0; mt < 4; mt++)
#pragma unroll
                    for (int nt = 0; nt < 4; nt++)
                        mma16816(acc[mt][nt], af[mt], bfrag[kh][nt >> 1] + (nt & 1) * 2);
            }

            if (t == 8 && q < 7) {
                __syncthreads();
                load_B((q + 1) * 64);
                CP_COMMIT();
            }
        }
    }

    const float wsc = 0.014731391274719736f;  // 1/sqrt(4608)
    const int y = y0 + wn;
#pragma unroll
    for (int mt = 0; mt < 4; mt++) {
        const int rr   = wm * 64 + mt * 16 + (lane >> 2);
        const int o_lo = o0 + rr;
        const int o_hi = o_lo + 8;
        const float d0 = g_d[b * COUT + o_lo] * wsc;
        const float d1 = g_d[b * COUT + o_hi] * wsc;
#pragma unroll
        for (int nt = 0; nt < 4; nt++) {
            const int xcol = nt * 8 + (lane & 3) * 2;
            float2 v0 = make_float2(acc[mt][nt][0] * d0, acc[mt][nt][1] * d0);
            float2 v1 = make_float2(acc[mt][nt][2] * d1, acc[mt][nt][3] * d1);
            *reinterpret_cast<float2*>(
                &out[(((long)b * COUT + o_lo) * 32 + y) * 32 + xcol]) = v0;
            *reinterpret_cast<float2*>(
                &out[(((long)b * COUT + o_hi) * 32 + y) * 32 + xcol]) = v1;
        }
    }
}

// ---------------------------------------------------------------------------
extern "C" void kernel_launch(void* const* d_in, const int* in_sizes, int n_in,
                              void* d_out, int out_size) {
    const float* x      = (const float*)d_in[0];  // [16,512,32,32]
    const float* style  = (const float*)d_in[1];  // [16,512]
    const float* aff_w  = (const float*)d_in[2];  // [512,512]
    const float* aff_b  = (const float*)d_in[3];  // [512]
    const float* cw     = (const float*)d_in[4];  // [512,512,3,3]
    float* out          = (float*)d_out;          // [16,512,32,32]

    cudaFuncSetAttribute(k_conv_mma,
                         cudaFuncAttributeMaxDynamicSharedMemorySize,
                         SMEMSZ);

    k_prep1<<<320, 256>>>(cw, style, aff_w, aff_b);
    k_prep2<<<dim3(Bsz, 17, 8), 256>>>(x);
    k_conv_mma<<<dim3(COUT / 128, 16, Bsz), 128, SMEMSZ>>>(out);
}